// round 3
// baseline (speedup 1.0000x reference)
#include <cuda_runtime.h>
#include <cuda_bf16.h>

// PatchMatch (b=1, c=192, h=w=128); fixed: iteration_count=2, minWH=127, is_final=1.
// 28 eval steps; 8 fresh candidates/pixel/step (center carried as coord+score).
// One warp per pixel, 4 lanes per candidate -> all candidates in flight at once.

#define C 192
#define NF4 48          // 192 floats = 48 float4
#define H 128
#define W 128
#define NPIX (H * W)

__device__ float4 g_in_t4[NPIX * NF4];    // pixel-major input  [p][48]
__device__ float4 g_ref_t4[NPIX * NF4];   // pixel-major ref    [p][48]
__device__ int    g_coord[2][NPIX];       // packed y*128+x, double-buffered
__device__ float  g_score[NPIX];          // score of current coord

__constant__ int c_YOFF[9] = {-1, -1, -1, 0, 0, 0, 1, 1, 1};
__constant__ int c_XOFF[9] = {-1, 0, 1, -1, 0, 1, -1, 0, 1};
__constant__ int c_DX[9]   = {0, -1, -1, 0, 0, 0, 1, 1, 0};
__constant__ int c_DY[9]   = {1, 0, 0, 1, 0, -1, 0, 0, -1};

// ---------------------------------------------------------------------------
__global__ void transpose_kernel(const float* __restrict__ in, float* __restrict__ out) {
    __shared__ float tile[32][33];
    int p0 = blockIdx.x * 32;
    int c0 = blockIdx.y * 32;
    tile[threadIdx.y][threadIdx.x] = in[(c0 + threadIdx.y) * NPIX + (p0 + threadIdx.x)];
    __syncthreads();
    out[(size_t)(p0 + threadIdx.y) * C + (c0 + threadIdx.x)] = tile[threadIdx.x][threadIdx.y];
}

// ---------------------------------------------------------------------------
// Shared dot-product order: lane handles float4 indices l, l+4, ..., l+44.
// MUST be identical everywhere so equal coords give bit-identical scores.
__device__ __forceinline__ float dot48(const float4* A, const float4* __restrict__ r4) {
    float s = 0.f;
#pragma unroll
    for (int i = 0; i < 12; i++) {
        float4 r = r4[4 * i];
        float4 a = A[i];
        s = fmaf(a.x, r.x, s); s = fmaf(a.y, r.y, s);
        s = fmaf(a.z, r.z, s); s = fmaf(a.w, r.w, s);
    }
    return s;
}

// ---------------------------------------------------------------------------
__global__ __launch_bounds__(128) void init_kernel(const float* __restrict__ inref_x,
                                                   const float* __restrict__ inref_y) {
    int warp = blockIdx.x * 4 + (threadIdx.x >> 5);
    int lane = threadIdx.x & 31;
    int l = lane & 3;
    int p = warp;
    int cc = ((int)inref_y[p] << 7) + (int)inref_x[p];

    const float4* __restrict__ a4 = g_in_t4 + (size_t)p * NF4 + l;
    float4 A[12];
#pragma unroll
    for (int i = 0; i < 12; i++) A[i] = a4[4 * i];

    float s = dot48(A, g_ref_t4 + (size_t)cc * NF4 + l);
    s += __shfl_xor_sync(0xffffffffu, s, 1);
    s += __shfl_xor_sync(0xffffffffu, s, 2);
    if (lane == 0) { g_coord[0][p] = cc; g_score[p] = s; }
}

// ---------------------------------------------------------------------------
__device__ __forceinline__ int reflect128(int t) {
    if (t < 0) t = -t;
    if (t > 127) t = 254 - t;
    return t;
}

// One warp per pixel; lane group g (4 lanes) evaluates candidate j(g).
// MODE 0 = propagation (dilated neighbors, reflect), MODE 1 = random search.
template <int MODE>
__global__ __launch_bounds__(128, 5) void eval_kernel(int k, int m, int cur, int nxt) {
    int warp = blockIdx.x * 4 + (threadIdx.x >> 5);
    int lane = threadIdx.x & 31;
    int g = lane >> 2, l = lane & 3;
    int j = g + (g >> 2);             // 0,1,2,3,5,6,7,8 (skip carried center 4)
    int p = warp;
    int y = p >> 7, x = p & 127;

    const float4* __restrict__ a4 = g_in_t4 + (size_t)p * NF4 + l;
    float4 A[12];
#pragma unroll
    for (int i = 0; i < 12; i++) A[i] = a4[4 * i];

    const int* __restrict__ cb = g_coord[cur];
    int myc = cb[p];
    float sc = g_score[p];

    int cc;
    if (MODE == 0) {
        int ny = reflect128(y + k * (j / 3 - 1));
        int nx = reflect128(x + k * (j % 3 - 1));
        cc = cb[(ny << 7) + nx];
    } else {
        int x0 = myc & 127, y0 = myc >> 7;
        int cx = (x0 + k * c_XOFF[j] + m * c_DX[j] + 128) & 127;
        int cy = (y0 + k * c_YOFF[j] + m * c_DY[j] + 128) & 127;
        cc = (cy << 7) | cx;
    }

    float s = dot48(A, g_ref_t4 + (size_t)cc * NF4 + l);
    // intra-group sum: all 4 lanes of the group hold the candidate score
    s += __shfl_xor_sync(0xffffffffu, s, 1);
    s += __shfl_xor_sync(0xffffffffu, s, 2);

    // warp-wide argmax, first-occurrence (lowest j wins ties)
    float best = s; int bestj = j; int bestc = cc;
#pragma unroll
    for (int d = 4; d < 32; d <<= 1) {
        float so = __shfl_xor_sync(0xffffffffu, best, d);
        int   jo = __shfl_xor_sync(0xffffffffu, bestj, d);
        int   co = __shfl_xor_sync(0xffffffffu, bestc, d);
        if (so > best || (so == best && jo < bestj)) { best = so; bestj = jo; bestc = co; }
    }
    // carried center candidate (j = 4)
    if (sc > best || (sc == best && bestj > 4)) { best = sc; bestc = myc; }

    if (lane == 0) { g_coord[nxt][p] = bestc; g_score[p] = best; }
}

// ---------------------------------------------------------------------------
__global__ void final_kernel(int cur, float* __restrict__ out, int out_size) {
    int p = blockIdx.x * blockDim.x + threadIdx.x;
    if (p < NPIX) {
        if (p < out_size)        out[p] = (float)g_coord[cur][p];
        if (NPIX + p < out_size) out[NPIX + p] = g_score[p];
    }
}

// ---------------------------------------------------------------------------
extern "C" void kernel_launch(void* const* d_in, const int* in_sizes, int n_in,
                              void* d_out, int out_size) {
    const float* input_map = (const float*)d_in[0];
    const float* ref_map   = (const float*)d_in[1];
    const float* inref_x   = (const float*)d_in[2];
    const float* inref_y   = (const float*)d_in[3];

    float* in_t;  cudaGetSymbolAddress((void**)&in_t,  g_in_t4);
    float* ref_t; cudaGetSymbolAddress((void**)&ref_t, g_ref_t4);

    dim3 tb(32, 32);
    dim3 tg(NPIX / 32, C / 32);
    transpose_kernel<<<tg, tb>>>(input_map, in_t);
    transpose_kernel<<<tg, tb>>>(ref_map, ref_t);
    init_kernel<<<NPIX / 4, 128>>>(inref_x, inref_y);

    const int grid = NPIX / 4;   // warp per pixel, 4 warps per 128-thread block
    int cur = 0;
    for (int prop_iter = 0; prop_iter < 2; prop_iter++) {
        for (int k = 1; k <= 127; k *= 2) {
            eval_kernel<0><<<grid, 128>>>(k, 0, cur, cur ^ 1);
            cur ^= 1;
        }
        for (int k = 1; k <= 127; k *= 2) {
            int m = prop_iter % k;
            eval_kernel<1><<<grid, 128>>>(k, m, cur, cur ^ 1);
            cur ^= 1;
        }
    }
    final_kernel<<<NPIX / 256 + 1, 256>>>(cur, (float*)d_out, out_size);
}

// round 4
// speedup vs baseline: 1.1966x; 1.1966x over previous
#include <cuda_runtime.h>
#include <cuda_bf16.h>

// PatchMatch (b=1, c=192, h=w=128); fixed: iteration_count=2, minWH=127, is_final=1.
// 28 eval steps; 8 fresh candidates/pixel/step (center carried as coord+score).
// Warp per pixel, lane = channel slice (float2 x3), all 8 candidates in flight.

#define C 192
#define NF2 96          // 192 floats = 96 float2
#define H 128
#define W 128
#define NPIX (H * W)

__device__ float2 g_in_t2[NPIX * NF2];    // pixel-major input  [p][96]
__device__ float2 g_ref_t2[NPIX * NF2];   // pixel-major ref    [p][96]
__device__ int    g_coord[2][NPIX];       // packed y*128+x, double-buffered
__device__ float  g_score[NPIX];          // score of current coord

__constant__ int c_YOFF[9] = {-1, -1, -1, 0, 0, 0, 1, 1, 1};
__constant__ int c_XOFF[9] = {-1, 0, 1, -1, 0, 1, -1, 0, 1};
__constant__ int c_DX[9]   = {0, -1, -1, 0, 0, 0, 1, 1, 0};
__constant__ int c_DY[9]   = {1, 0, 0, 1, 0, -1, 0, 0, -1};

// ---------------------------------------------------------------------------
__global__ void transpose_kernel(const float* __restrict__ in, float* __restrict__ out) {
    __shared__ float tile[32][33];
    int p0 = blockIdx.x * 32;
    int c0 = blockIdx.y * 32;
    tile[threadIdx.y][threadIdx.x] = in[(c0 + threadIdx.y) * NPIX + (p0 + threadIdx.x)];
    __syncthreads();
    out[(size_t)(p0 + threadIdx.y) * C + (c0 + threadIdx.x)] = tile[threadIdx.x][threadIdx.y];
}

// ---------------------------------------------------------------------------
// Per-lane partial dot product; order fixed so equal coords -> identical bits.
__device__ __forceinline__ float dot6(float2 A0, float2 A1, float2 A2,
                                      const float2* __restrict__ r2) {
    float2 r0 = r2[0], r1 = r2[32], rr = r2[64];
    float s;
    s = A0.x * r0.x;         s = fmaf(A0.y, r0.y, s);
    s = fmaf(A1.x, r1.x, s); s = fmaf(A1.y, r1.y, s);
    s = fmaf(A2.x, rr.x, s); s = fmaf(A2.y, rr.y, s);
    return s;
}

__device__ __forceinline__ float warpsum(float s) {
    s += __shfl_xor_sync(0xffffffffu, s, 16);
    s += __shfl_xor_sync(0xffffffffu, s, 8);
    s += __shfl_xor_sync(0xffffffffu, s, 4);
    s += __shfl_xor_sync(0xffffffffu, s, 2);
    s += __shfl_xor_sync(0xffffffffu, s, 1);
    return s;
}

// ---------------------------------------------------------------------------
__global__ __launch_bounds__(256) void init_kernel(const float* __restrict__ inref_x,
                                                   const float* __restrict__ inref_y) {
    int warp = blockIdx.x * 8 + (threadIdx.x >> 5);
    int lane = threadIdx.x & 31;
    int p = warp;
    int cc = ((int)inref_y[p] << 7) + (int)inref_x[p];

    const float2* __restrict__ a2 = g_in_t2 + (size_t)p * NF2 + lane;
    float2 A0 = a2[0], A1 = a2[32], A2 = a2[64];
    float s = warpsum(dot6(A0, A1, A2, g_ref_t2 + (size_t)cc * NF2 + lane));
    if (lane == 0) { g_coord[0][p] = cc; g_score[p] = s; }
}

// ---------------------------------------------------------------------------
__device__ __forceinline__ int reflect128(int t) {
    if (t < 0) t = -t;
    if (t > 127) t = 254 - t;
    return t;
}

// Warp per pixel; 8 fresh candidates concurrently (independent accumulators).
// MODE 0 = propagation (dilated neighbors, reflect), MODE 1 = random search.
template <int MODE>
__global__ __launch_bounds__(256) void eval_kernel(int k, int m, int cur, int nxt) {
    int warp = blockIdx.x * 8 + (threadIdx.x >> 5);
    int lane = threadIdx.x & 31;
    int p = warp;
    int y = p >> 7, x = p & 127;

    const float2* __restrict__ a2 = g_in_t2 + (size_t)p * NF2 + lane;
    float2 A0 = a2[0], A1 = a2[32], A2 = a2[64];

    const int* __restrict__ cb = g_coord[cur];
    int myc = cb[p];
    float sc = g_score[p];

    // Candidate coords (uniform across the warp); q = 0..7 maps to j = q + (q>=4)
    int cc[8];
#pragma unroll
    for (int q = 0; q < 8; q++) {
        int j = q + (q >> 2);
        if (MODE == 0) {
            int ny = reflect128(y + k * (j / 3 - 1));
            int nx = reflect128(x + k * (j % 3 - 1));
            cc[q] = cb[(ny << 7) + nx];
        } else {
            int x0 = myc & 127, y0 = myc >> 7;
            int cx = (x0 + k * c_XOFF[j] + m * c_DX[j] + 128) & 127;
            int cy = (y0 + k * c_YOFF[j] + m * c_DY[j] + 128) & 127;
            cc[q] = (cy << 7) | cx;
        }
    }

    // All 8 partial dot products independent -> loads overlap fully.
    float s[8];
#pragma unroll
    for (int q = 0; q < 8; q++)
        s[q] = dot6(A0, A1, A2, g_ref_t2 + (size_t)cc[q] * NF2 + lane);

    // Butterfly-reduce all 8 sums together (depth 5, independent per level).
#pragma unroll
    for (int d = 16; d >= 1; d >>= 1) {
#pragma unroll
        for (int q = 0; q < 8; q++)
            s[q] += __shfl_xor_sync(0xffffffffu, s[q], d);
    }

    // First-occurrence argmax over order [0,1,2,3, center(4), 5,6,7,8].
    float best = s[0]; int bestc = cc[0];
#pragma unroll
    for (int q = 1; q < 4; q++)
        if (s[q] > best) { best = s[q]; bestc = cc[q]; }
    if (sc > best) { best = sc; bestc = myc; }
#pragma unroll
    for (int q = 4; q < 8; q++)
        if (s[q] > best) { best = s[q]; bestc = cc[q]; }

    if (lane == 0) { g_coord[nxt][p] = bestc; g_score[p] = best; }
}

// ---------------------------------------------------------------------------
__global__ void final_kernel(int cur, float* __restrict__ out, int out_size) {
    int p = blockIdx.x * blockDim.x + threadIdx.x;
    if (p < NPIX) {
        if (p < out_size)        out[p] = (float)g_coord[cur][p];
        if (NPIX + p < out_size) out[NPIX + p] = g_score[p];
    }
}

// ---------------------------------------------------------------------------
extern "C" void kernel_launch(void* const* d_in, const int* in_sizes, int n_in,
                              void* d_out, int out_size) {
    const float* input_map = (const float*)d_in[0];
    const float* ref_map   = (const float*)d_in[1];
    const float* inref_x   = (const float*)d_in[2];
    const float* inref_y   = (const float*)d_in[3];

    float* in_t;  cudaGetSymbolAddress((void**)&in_t,  g_in_t2);
    float* ref_t; cudaGetSymbolAddress((void**)&ref_t, g_ref_t2);

    dim3 tb(32, 32);
    dim3 tg(NPIX / 32, C / 32);
    transpose_kernel<<<tg, tb>>>(input_map, in_t);
    transpose_kernel<<<tg, tb>>>(ref_map, ref_t);
    init_kernel<<<NPIX / 8, 256>>>(inref_x, inref_y);

    const int grid = NPIX / 8;   // warp per pixel, 8 warps per 256-thread block
    int cur = 0;
    for (int prop_iter = 0; prop_iter < 2; prop_iter++) {
        for (int k = 1; k <= 127; k *= 2) {
            eval_kernel<0><<<grid, 256>>>(k, 0, cur, cur ^ 1);
            cur ^= 1;
        }
        for (int k = 1; k <= 127; k *= 2) {
            int m = prop_iter % k;
            eval_kernel<1><<<grid, 256>>>(k, m, cur, cur ^ 1);
            cur ^= 1;
        }
    }
    final_kernel<<<NPIX / 256 + 1, 256>>>(cur, (float*)d_out, out_size);
}